// round 15
// baseline (speedup 1.0000x reference)
#include <cuda_runtime.h>
#include <math.h>

#define BB 4
#define HH 8
#define LQ 1024
#define LK 2048
#define DM 128
#define EPSV 1e-5f

// ---------------- scratch (device globals; no runtime alloc) ----------------
__device__ float g_Q [BB*HH*LQ*16];   // head-major [bh][l][16]
__device__ float g_K [BB*HH*LK*16];
__device__ float g_V [BB*HH*LK*16];
__device__ float g_V2[BB*HH*LQ*16];
__device__ float g_o1[BB*LQ*DM];
__device__ float g_o2[BB*LK*DM];

// swizzled word index of float4 #q (q=0..3) in staged row k (16 floats/row)
__device__ __forceinline__ int swz4(int k, int q) {
    return (k << 4) + (((q ^ (k >> 1)) & 3) << 2);
}

__device__ __forceinline__ void cpasync16(unsigned dst, const void* src) {
    asm volatile("cp.async.ca.shared.global [%0], [%1], 16;\n" :: "r"(dst), "l"(src));
}
__device__ __forceinline__ void cpcommit() {
    asm volatile("cp.async.commit_group;\n" ::: "memory");
}
template<int N>
__device__ __forceinline__ void cpwait() {
    asm volatile("cp.async.wait_group %0;\n" :: "n"(N) : "memory");
}

// ---------------- fused 4-way projection ------------------------------------
__global__ __launch_bounds__(256)
void proj4_kernel(const float* __restrict__ q,  const float* __restrict__ k,
                  const float* __restrict__ v,  const float* __restrict__ v2,
                  const float* __restrict__ WQ, const float* __restrict__ bQ,
                  const float* __restrict__ WK, const float* __restrict__ bK,
                  const float* __restrict__ WV, const float* __restrict__ bV,
                  const float* __restrict__ WV2,const float* __restrict__ bV2,
                  float* pQ, float* pK, float* pV, float* pV2)
{
    const float *X, *W, *bias; float* Yh; int L;
    switch (blockIdx.z) {
        case 0:  X = q;  W = WQ;  bias = bQ;  Yh = pQ;  L = LQ; break;
        case 1:  X = k;  W = WK;  bias = bK;  Yh = pK;  L = LK; break;
        case 2:  X = v;  W = WV;  bias = bV;  Yh = pV;  L = LK; break;
        default: X = v2; W = WV2; bias = bV2; Yh = pV2; L = LQ; break;
    }
    int l0 = blockIdx.x * 16;
    if (l0 >= L) return;

    extern __shared__ float sm[];
    float* Ws = sm;               // 128 x 132 (transposed, padded)
    float* Xs = sm + 128*132;     // 16 x 128
    int tid = threadIdx.x;
    int b = blockIdx.y;

    for (int i = tid; i < 128*128; i += 256) {
        int cc = i >> 7, c = i & 127;
        Ws[c*132 + cc] = W[i];
    }
    const float4* xb = (const float4*)(X + ((size_t)(b*L + l0))*DM);
    float4* Xs4 = (float4*)Xs;
    for (int i = tid; i < 16*32; i += 256) Xs4[i] = xb[i];
    __syncthreads();

    int c  = tid & 127;
    int r0 = tid >> 7;
    float acc[8];
    float bv = bias[c];
#pragma unroll
    for (int j = 0; j < 8; j++) acc[j] = bv;
    for (int cc = 0; cc < 128; cc += 4) {
        float4 w4 = *(const float4*)&Ws[c*132 + cc];
#pragma unroll
        for (int j = 0; j < 8; j++) {
            float4 x4 = *(const float4*)&Xs[(r0 + 2*j)*128 + cc];
            float a = acc[j];
            a = fmaf(x4.x, w4.x, a);
            a = fmaf(x4.y, w4.y, a);
            a = fmaf(x4.z, w4.z, a);
            a = fmaf(x4.w, w4.w, a);
            acc[j] = a;
        }
    }
    int h = c >> 4, d = c & 15;
#pragma unroll
    for (int j = 0; j < 8; j++) {
        int l = l0 + r0 + 2*j;
        Yh[((size_t)(b*HH + h)*L + l)*16 + d] = acc[j];
    }
}

// ---------------- fused scores + entmax1.5 + (A@V) --------------------------
// ROWS=10 / 320 threads so 2+ CTAs co-reside per SM (barrier overlap).
template<int LCOL>
__global__ __launch_bounds__(320)
void attn_kernel(const float* __restrict__ RowM, const float* __restrict__ ColM,
                 const float* __restrict__ Vm, float* __restrict__ Aout,
                 float* __restrict__ Omid, int Lrow)
{
    constexpr int ROWS = 10;
    constexpr int THREADS = 320;
    constexpr int NT4 = LCOL / 128;      // float4s per lane per row (phase 2)
    constexpr int NC  = LCOL / 128;      // chunks of 128 columns
    extern __shared__ float sm[];
    float* S   = sm;                      // ROWS * LCOL
    float* Ck0 = sm + ROWS*LCOL;          // 2048 floats (swizzled 128x16)
    float* Ck1 = Ck0 + 2048;              // 2048 floats
    float* Sp  = Ck1 + 2048;              // 384 floats: stats + partials

    int tid = threadIdx.x, warp = tid >> 5, lane = tid & 31;
    int bh = blockIdx.z * HH + blockIdx.y;
    int r0 = blockIdx.x * ROWS;

    unsigned ckA[2];
    ckA[0] = (unsigned)__cvta_generic_to_shared(Ck0);
    ckA[1] = (unsigned)__cvta_generic_to_shared(Ck1);

    const float* colbase = ColM + (size_t)bh*LCOL*16;
    const float* vbase   = Vm   + (size_t)bh*LCOL*16;

    // stage one 128x16 chunk (512 float4 transfers)
#define STAGE_CHUNK(buf, base, chunk)                                          \
    do {                                                                       \
        for (int i_ = tid; i_ < 512; i_ += THREADS) {                          \
            int kk_ = i_ >> 2, qq_ = i_ & 3;                                   \
            cpasync16(ckA[buf] + (unsigned)swz4(kk_, qq_)*4u,                  \
                      (base) + (size_t)((chunk)*128 + kk_)*16 + qq_*4);        \
        }                                                                      \
        cpcommit();                                                            \
    } while (0)

    // ---- phase 1: score tile (2 rows/warp, 64-col half) + running stats ----
    {
        int rowg = warp % 5, cs = warp / 5;   // 5 row-groups x 2 col-halves
        float qa[2][16];
#pragma unroll
        for (int j = 0; j < 2; j++) {
            int rr = r0 + rowg*2 + j; if (rr > Lrow - 1) rr = Lrow - 1;
            const float4* qr = (const float4*)(RowM + ((size_t)bh*Lrow + rr)*16);
#pragma unroll
            for (int u = 0; u < 4; u++) {
                float4 a = qr[u];
                qa[j][u*4+0] = a.x; qa[j][u*4+1] = a.y;
                qa[j][u*4+2] = a.z; qa[j][u*4+3] = a.w;
            }
        }
        float s1s[2] = {0.f, 0.f};
        float s2s[2] = {0.f, 0.f};

        STAGE_CHUNK(0, colbase, 0);
        STAGE_CHUNK(1, colbase, 1);

        for (int c = 0; c < NC; c++) {
            if (c + 1 < NC) cpwait<1>(); else cpwait<0>();
            __syncthreads();
            const float* Ck = (c & 1) ? Ck1 : Ck0;
#pragma unroll
            for (int t = 0; t < 2; t++) {
                int kl = cs*64 + t*32 + lane;
                float s0 = 0.f, s1 = 0.f;
#pragma unroll
                for (int u = 0; u < 4; u++) {
                    float4 k4 = *(const float4*)&Ck[swz4(kl, u)];
                    s0 = fmaf(qa[0][u*4+0], k4.x, s0); s0 = fmaf(qa[0][u*4+1], k4.y, s0);
                    s0 = fmaf(qa[0][u*4+2], k4.z, s0); s0 = fmaf(qa[0][u*4+3], k4.w, s0);
                    s1 = fmaf(qa[1][u*4+0], k4.x, s1); s1 = fmaf(qa[1][u*4+1], k4.y, s1);
                    s1 = fmaf(qa[1][u*4+2], k4.z, s1); s1 = fmaf(qa[1][u*4+3], k4.w, s1);
                }
                float v0 = 0.125f*s0, v1 = 0.125f*s1;
                S[(rowg*2+0)*LCOL + c*128 + kl] = v0;
                S[(rowg*2+1)*LCOL + c*128 + kl] = v1;
                s1s[0] += v0; s2s[0] = fmaf(v0, v0, s2s[0]);
                s1s[1] += v1; s2s[1] = fmaf(v1, v1, s2s[1]);
            }
            __syncthreads();
            if (c + 2 < NC) STAGE_CHUNK(c & 1, colbase, c + 2);
        }
        // reduce per-row stats across lanes, park in Sp
#pragma unroll
        for (int j = 0; j < 2; j++) {
#pragma unroll
            for (int o = 16; o > 0; o >>= 1) {
                s1s[j] += __shfl_xor_sync(0xffffffffu, s1s[j], o);
                s2s[j] += __shfl_xor_sync(0xffffffffu, s2s[j], o);
            }
        }
        if (lane == 0) {
#pragma unroll
            for (int j = 0; j < 2; j++) {
                Sp[cs*10 + rowg*2 + j]      = s1s[j];   // sum
                Sp[20 + cs*10 + rowg*2 + j] = s2s[j];   // sumsq
            }
        }
    }

    // prefetch V chunks 0,1 so they land during phase 2
    STAGE_CHUNK(0, vbase, 0);
    STAGE_CHUNK(1, vbase, 1);
    __syncthreads();    // stats visible to all warps

    // ---- phase 2: entmax1.5 per row (warp = row); stats pre-computed -------
    {
        float4* Srow4 = (float4*)(S + warp*LCOL);

        float s1 = Sp[warp] + Sp[10 + warp];
        float s2 = Sp[20 + warp] + Sp[30 + warp];

        const float n = (float)LCOL;
        float mean = s1 / n;
        float var  = s2 / n - mean*mean;
        float delta = (1.f - n*var) / n;
        float tau = mean - sqrtf(fmaxf(delta, 0.f));

        // Newton on F(tau) = sum relu(x - tau)^2 - 1  (monotone from below)
        for (int it = 0; it < 12; it++) {
            float F = 0.f, G = 0.f;
#pragma unroll
            for (int t = 0; t < NT4; t++) {
                float4 x = Srow4[lane + 32*t];
                float d0 = fmaxf(x.x - tau, 0.f), d1 = fmaxf(x.y - tau, 0.f);
                float d2 = fmaxf(x.z - tau, 0.f), d3 = fmaxf(x.w - tau, 0.f);
                F = fmaf(d0, d0, F); G += d0;
                F = fmaf(d1, d1, F); G += d1;
                F = fmaf(d2, d2, F); G += d2;
                F = fmaf(d3, d3, F); G += d3;
            }
#pragma unroll
            for (int o = 16; o > 0; o >>= 1) {
                F += __shfl_xor_sync(0xffffffffu, F, o);
                G += __shfl_xor_sync(0xffffffffu, G, o);
            }
            float step = (F - 1.f) / (2.f*G);
            tau += step;
            if (fabsf(step) < 1e-6f) break;
        }

        int row = r0 + warp;
        bool ok = row < Lrow;
        float4* Arow4 = (float4*)(Aout + ((size_t)bh*Lrow + (ok ? row : 0))*LCOL);
#pragma unroll
        for (int t = 0; t < NT4; t++) {
            float4 x = Srow4[lane + 32*t];
            float d0 = fmaxf(x.x - tau, 0.f), d1 = fmaxf(x.y - tau, 0.f);
            float d2 = fmaxf(x.z - tau, 0.f), d3 = fmaxf(x.w - tau, 0.f);
            float4 p = make_float4(d0*d0, d1*d1, d2*d2, d3*d3);
            Srow4[lane + 32*t] = p;
            if (ok) __stcs(&Arow4[lane + 32*t], p);
        }
    }
    __syncthreads();

    // ---- phase 3: split-k  O[row][d] = sum_k p[k] V[k][d] ------------------
    // warp w: row group rg = w%5 (2 rows), k-slice ks = w/5 (64 cols/chunk)
    {
        int rg = warp % 5, ks = warp / 5;
        float o[2][16];
#pragma unroll
        for (int r = 0; r < 2; r++)
#pragma unroll
            for (int d = 0; d < 16; d++) o[r][d] = 0.f;

        for (int c = 0; c < NC; c++) {
            if (c + 1 < NC) cpwait<1>(); else cpwait<0>();
            __syncthreads();
            const float* Ck = (c & 1) ? Ck1 : Ck0;
#pragma unroll
            for (int t = 0; t < 2; t++) {
                int col = ks*64 + t*32 + lane;
                float p0 = S[(rg*2+0)*LCOL + c*128 + col];
                float p1 = S[(rg*2+1)*LCOL + c*128 + col];
                float4 v0 = *(const float4*)&Ck[swz4(col,0)];
                float4 v1 = *(const float4*)&Ck[swz4(col,1)];
                float4 v2 = *(const float4*)&Ck[swz4(col,2)];
                float4 v3 = *(const float4*)&Ck[swz4(col,3)];
                float vv[16] = {v0.x,v0.y,v0.z,v0.w, v1.x,v1.y,v1.z,v1.w,
                                v2.x,v2.y,v2.z,v2.w, v3.x,v3.y,v3.z,v3.w};
#pragma unroll
                for (int d = 0; d < 16; d++) {
                    o[0][d] = fmaf(p0, vv[d], o[0][d]);
                    o[1][d] = fmaf(p1, vv[d], o[1][d]);
                }
            }
            __syncthreads();
            if (c + 2 < NC) STAGE_CHUNK(c & 1, vbase, c + 2);
        }

        // butterfly-reduce each accumulator over lanes
#pragma unroll
        for (int r = 0; r < 2; r++)
#pragma unroll
            for (int d = 0; d < 16; d++)
#pragma unroll
                for (int off = 16; off > 0; off >>= 1)
                    o[r][d] += __shfl_xor_sync(0xffffffffu, o[r][d], off);

        float val[2];
#pragma unroll
        for (int r = 0; r < 2; r++) {
            float vv = 0.f;
#pragma unroll
            for (int d = 0; d < 16; d++) if (lane == d) vv = o[r][d];
            val[r] = vv;
        }
        if (lane < 16) {
#pragma unroll
            for (int r = 0; r < 2; r++)
                Sp[40 + ks*(ROWS*16) + (rg*2+r)*16 + lane] = val[r];
        }
    }
    __syncthreads();
    // combine 2 k-slices, write Omid
    for (int i = tid; i < ROWS*16; i += THREADS) {
        float s = Sp[40 + i] + Sp[40 + ROWS*16 + i];
        int r = i >> 4, d = i & 15;
        int row = r0 + r;
        if (row < Lrow) {
            int b = blockIdx.z, h = blockIdx.y;
            Omid[((size_t)(b*Lrow + row))*DM + h*16 + d] = s;
        }
    }
#undef STAGE_CHUNK
}

// ---------------- fused final x2: relu(LN(X@WO + bO + R@WR)) ----------------
// 64 rows/CTA, 256 threads, thread tile 8 rows x 4 cols, float4 over cc
__global__ __launch_bounds__(256)
void final2_kernel(const float* __restrict__ po1, const float* __restrict__ po2,
                   const float* __restrict__ qin, const float* __restrict__ kin,
                   const float* __restrict__ WO,  const float* __restrict__ bOv,
                   const float* __restrict__ WR,
                   const float* __restrict__ WO2, const float* __restrict__ bO2,
                   const float* __restrict__ WR2,
                   const float* __restrict__ gamma, const float* __restrict__ beta,
                   float* __restrict__ out)
{
    int ssel = blockIdx.y;
    int rows = ssel ? BB*LK : BB*LQ;
    size_t row0 = (size_t)blockIdx.x * 64;
    if (row0 >= (size_t)rows) return;
    const float* Xmid  = ssel ? po2 : po1;
    const float* Resid = ssel ? kin : qin;
    const float* WOp   = ssel ? WO2 : WO;
    const float* bOp   = ssel ? bO2 : bOv;
    const float* WRp   = ssel ? WR2 : WR;
    float* dst = out + (ssel ? (size_t)BB*LQ*DM : 0);

    extern __shared__ float sm[];
    float* Wo = sm;               // 128 x 132 transposed
    float* Wr = sm + 128*132;     // 128 x 132 transposed
    float* Xs = sm + 2*128*132;   // 64 x 128
    float* Rs = Xs + 64*128;      // 64 x 128
    float* Ys = Xs;               // reused after GEMM
    int tid = threadIdx.x;

    for (int i = tid; i < 128*128; i += 256) {
        int cc = i >> 7, c = i & 127;
        Wo[c*132 + cc] = WOp[i];
        Wr[c*132 + cc] = WRp[i];
    }
    {
        const float4* xb = (const float4*)(Xmid  + row0*DM);
        const float4* rb = (const float4*)(Resid + row0*DM);
        float4* Xs4 = (float4*)Xs; float4* Rs4 = (float4*)Rs;
        for (int i = tid; i < 64*32; i += 256) { Xs4[i] = xb[i]; Rs4[i] = rb[i]; }
    }
    __syncthreads();

    int c0  = (tid & 31) * 4;     // 4 consecutive output cols
    int r0t = (tid >> 5) * 8;     // 8 rows
    float acc[8][4];
#pragma unroll
    for (int j = 0; j < 4; j++) {
        float bv = bOp[c0 + j];
#pragma unroll
        for (int r = 0; r < 8; r++) acc[r][j] = bv;
    }
    for (int cc = 0; cc < 128; cc += 4) {
        float4 wo[4], wr[4];
#pragma unroll
        for (int j = 0; j < 4; j++) {
            wo[j] = *(const float4*)&Wo[(c0+j)*132 + cc];
            wr[j] = *(const float4*)&Wr[(c0+j)*132 + cc];
        }
#pragma unroll
        for (int r = 0; r < 8; r++) {
            float4 x4 = *(const float4*)&Xs[(r0t+r)*128 + cc];
            float4 r4 = *(const float4*)&Rs[(r0t+r)*128 + cc];
#pragma unroll
            for (int j = 0; j < 4; j++) {
                float a = acc[r][j];
                a = fmaf(x4.x, wo[j].x, a); a = fmaf(r4.x, wr[j].x, a);
                a = fmaf(x4.y, wo[j].y, a); a = fmaf(r4.y, wr[j].y, a);
                a = fmaf(x4.z, wo[j].z, a); a = fmaf(r4.z, wr[j].z, a);
                a = fmaf(x4.w, wo[j].w, a); a = fmaf(r4.w, wr[j].w, a);
                acc[r][j] = a;
            }
        }
    }
    __syncthreads();   // all reads of Xs/Rs done
#pragma unroll
    for (int r = 0; r < 8; r++)
        *(float4*)&Ys[(r0t+r)*128 + c0] =
            make_float4(acc[r][0], acc[r][1], acc[r][2], acc[r][3]);
    __syncthreads();

    int warp = tid >> 5, lane = tid & 31;
    for (int rr = warp; rr < 64; rr += 8) {
        float v0 = Ys[rr*DM + lane],      v1 = Ys[rr*DM + lane + 32];
        float v2 = Ys[rr*DM + lane + 64], v3 = Ys[rr*DM + lane + 96];
        float s = v0 + v1 + v2 + v3;
#pragma unroll
        for (int o = 16; o > 0; o >>= 1) s += __shfl_xor_sync(0xffffffffu, s, o);
        float mu = s * (1.f/128.f);
        float d0 = v0-mu, d1 = v1-mu, d2 = v2-mu, d3 = v3-mu;
        float vs = d0*d0 + d1*d1 + d2*d2 + d3*d3;
#pragma unroll
        for (int o = 16; o > 0; o >>= 1) vs += __shfl_xor_sync(0xffffffffu, vs, o);
        float inv = rsqrtf(vs * (1.f/128.f) + EPSV);
        float* drow = dst + (row0 + rr)*DM;
        drow[lane]      = fmaxf(gamma[lane]     *d0*inv + beta[lane],      0.f);
        drow[lane + 32] = fmaxf(gamma[lane + 32]*d1*inv + beta[lane + 32], 0.f);
        drow[lane + 64] = fmaxf(gamma[lane + 64]*d2*inv + beta[lane + 64], 0.f);
        drow[lane + 96] = fmaxf(gamma[lane + 96]*d3*inv + beta[lane + 96], 0.f);
    }
}

// ---------------- host launcher ----------------------------------------------
extern "C" void kernel_launch(void* const* d_in, const int* in_sizes, int n_in,
                              void* d_out, int out_size)
{
    const float* q    = (const float*)d_in[0];
    const float* k    = (const float*)d_in[1];
    const float* v    = (const float*)d_in[2];
    const float* v2   = (const float*)d_in[3];
    const float* W_Q  = (const float*)d_in[4];
    const float* b_Q  = (const float*)d_in[5];
    const float* W_K  = (const float*)d_in[6];
    const float* b_K  = (const float*)d_in[7];
    const float* W_V  = (const float*)d_in[8];
    const float* b_V  = (const float*)d_in[9];
    const float* W_V2 = (const float*)d_in[10];
    const float* b_V2 = (const float*)d_in[11];
    const float* W_O  = (const float*)d_in[12];
    const float* b_O  = (const float*)d_in[13];
    const float* W_O2 = (const float*)d_in[14];
    const float* b_O2 = (const float*)d_in[15];
    const float* W_R  = (const float*)d_in[16];
    const float* W_R2 = (const float*)d_in[17];
    const float* gamma= (const float*)d_in[18];
    const float* beta = (const float*)d_in[19];
    float* out = (float*)d_out;

    float *pQ, *pK, *pV, *pV2, *po1, *po2;
    cudaGetSymbolAddress((void**)&pQ,  g_Q);
    cudaGetSymbolAddress((void**)&pK,  g_K);
    cudaGetSymbolAddress((void**)&pV,  g_V);
    cudaGetSymbolAddress((void**)&pV2, g_V2);
    cudaGetSymbolAddress((void**)&po1, g_o1);
    cudaGetSymbolAddress((void**)&po2, g_o2);

    const int PROJ_SMEM = (128*132 + 16*128) * 4;               // 75776
    const int ATT1_SMEM = (10*LK + 2*2048 + 384) * 4;           // 99840
    const int ATT2_SMEM = (10*LQ + 2*2048 + 384) * 4;           // 58880
    const int FIN_SMEM  = (2*128*132 + 2*64*128) * 4;           // 200704
    cudaFuncSetAttribute(proj4_kernel,  cudaFuncAttributeMaxDynamicSharedMemorySize, PROJ_SMEM);
    cudaFuncSetAttribute(attn_kernel<LK>, cudaFuncAttributeMaxDynamicSharedMemorySize, ATT1_SMEM);
    cudaFuncSetAttribute(attn_kernel<LQ>, cudaFuncAttributeMaxDynamicSharedMemorySize, ATT2_SMEM);
    cudaFuncSetAttribute(final2_kernel, cudaFuncAttributeMaxDynamicSharedMemorySize, FIN_SMEM);

    proj4_kernel<<<dim3(LK/16, BB, 4), 256, PROJ_SMEM>>>(
        q, k, v, v2, W_Q, b_Q, W_K, b_K, W_V, b_V, W_V2, b_V2, pQ, pK, pV, pV2);

    // d_out layout: out [B,Lq,128] | out2 [B,Lk,128] | A [B,H,Lq,Lk] | A2 [B,H,Lk,Lq]
    float* Aout  = out + ((size_t)BB*LQ*DM + (size_t)BB*LK*DM);
    float* A2out = Aout + (size_t)BB*HH*LQ*LK;

    attn_kernel<LK><<<dim3((LQ + 9)/10, HH, BB), 320, ATT1_SMEM>>>(
        pQ, pK, pV,  Aout,  po1, LQ);
    attn_kernel<LQ><<<dim3((LK + 9)/10, HH, BB), 320, ATT2_SMEM>>>(
        pK, pQ, pV2, A2out, po2, LK);

    final2_kernel<<<dim3(BB*LK/64, 2), 256, FIN_SMEM>>>(
        po1, po2, q, k, W_O, b_O, W_R, W_O2, b_O2, W_R2, gamma, beta, out);
}

// round 16
// speedup vs baseline: 1.0532x; 1.0532x over previous
#include <cuda_runtime.h>
#include <math.h>

#define BB 4
#define HH 8
#define LQ 1024
#define LK 2048
#define DM 128
#define EPSV 1e-5f

// ---------------- scratch (device globals; no runtime alloc) ----------------
__device__ float g_Q [BB*HH*LQ*16];   // head-major [bh][l][16]
__device__ float g_K [BB*HH*LK*16];
__device__ float g_V [BB*HH*LK*16];
__device__ float g_V2[BB*HH*LQ*16];
__device__ float g_o1[BB*LQ*DM];
__device__ float g_o2[BB*LK*DM];

// swizzled word index of float4 #q (q=0..3) in staged row k (16 floats/row)
__device__ __forceinline__ int swz4(int k, int q) {
    return (k << 4) + (((q ^ (k >> 1)) & 3) << 2);
}

__device__ __forceinline__ void cpasync16(unsigned dst, const void* src) {
    asm volatile("cp.async.ca.shared.global [%0], [%1], 16;\n" :: "r"(dst), "l"(src));
}
__device__ __forceinline__ void cpcommit() {
    asm volatile("cp.async.commit_group;\n" ::: "memory");
}
template<int N>
__device__ __forceinline__ void cpwait() {
    asm volatile("cp.async.wait_group %0;\n" :: "n"(N) : "memory");
}

// ---------------- fused 4-way projection ------------------------------------
__global__ __launch_bounds__(256)
void proj4_kernel(const float* __restrict__ q,  const float* __restrict__ k,
                  const float* __restrict__ v,  const float* __restrict__ v2,
                  const float* __restrict__ WQ, const float* __restrict__ bQ,
                  const float* __restrict__ WK, const float* __restrict__ bK,
                  const float* __restrict__ WV, const float* __restrict__ bV,
                  const float* __restrict__ WV2,const float* __restrict__ bV2,
                  float* pQ, float* pK, float* pV, float* pV2)
{
    const float *X, *W, *bias; float* Yh; int L;
    switch (blockIdx.z) {
        case 0:  X = q;  W = WQ;  bias = bQ;  Yh = pQ;  L = LQ; break;
        case 1:  X = k;  W = WK;  bias = bK;  Yh = pK;  L = LK; break;
        case 2:  X = v;  W = WV;  bias = bV;  Yh = pV;  L = LK; break;
        default: X = v2; W = WV2; bias = bV2; Yh = pV2; L = LQ; break;
    }
    int l0 = blockIdx.x * 16;
    if (l0 >= L) return;

    extern __shared__ float sm[];
    float* Ws = sm;               // 128 x 132 (transposed, padded)
    float* Xs = sm + 128*132;     // 16 x 128
    int tid = threadIdx.x;
    int b = blockIdx.y;

    for (int i = tid; i < 128*128; i += 256) {
        int cc = i >> 7, c = i & 127;
        Ws[c*132 + cc] = W[i];
    }
    const float4* xb = (const float4*)(X + ((size_t)(b*L + l0))*DM);
    float4* Xs4 = (float4*)Xs;
    for (int i = tid; i < 16*32; i += 256) Xs4[i] = xb[i];
    __syncthreads();

    int c  = tid & 127;
    int r0 = tid >> 7;
    float acc[8];
    float bv = bias[c];
#pragma unroll
    for (int j = 0; j < 8; j++) acc[j] = bv;
    for (int cc = 0; cc < 128; cc += 4) {
        float4 w4 = *(const float4*)&Ws[c*132 + cc];
#pragma unroll
        for (int j = 0; j < 8; j++) {
            float4 x4 = *(const float4*)&Xs[(r0 + 2*j)*128 + cc];
            float a = acc[j];
            a = fmaf(x4.x, w4.x, a);
            a = fmaf(x4.y, w4.y, a);
            a = fmaf(x4.z, w4.z, a);
            a = fmaf(x4.w, w4.w, a);
            acc[j] = a;
        }
    }
    int h = c >> 4, d = c & 15;
#pragma unroll
    for (int j = 0; j < 8; j++) {
        int l = l0 + r0 + 2*j;
        Yh[((size_t)(b*HH + h)*L + l)*16 + d] = acc[j];
    }
}

// ---------------- fused scores + entmax1.5 + (A@V) --------------------------
// scores[r][c] = 0.125 * dot(Row[r], Col[c])  (128-col chunks; R11 layout)
template<int LCOL>
__global__ __launch_bounds__(640)
void attn_kernel(const float* __restrict__ RowM, const float* __restrict__ ColM,
                 const float* __restrict__ Vm, float* __restrict__ Aout,
                 float* __restrict__ Omid, int Lrow)
{
    constexpr int ROWS = 20;
    constexpr int THREADS = 640;
    constexpr int NT4 = LCOL / 128;      // float4s per lane per row (phase 2)
    constexpr int NC  = LCOL / 128;      // chunks of 128 columns
    extern __shared__ float sm[];
    float* S   = sm;                      // ROWS * LCOL
    float* Ck0 = sm + ROWS*LCOL;          // 2048 floats (swizzled 128x16)
    float* Ck1 = Ck0 + 2048;              // 2048 floats
    float* Sp  = Ck1 + 2048;              // 4 * ROWS*16 partials

    int tid = threadIdx.x, warp = tid >> 5, lane = tid & 31;
    int bh = blockIdx.z * HH + blockIdx.y;
    int r0 = blockIdx.x * ROWS;
    bool ldr = (tid < 512);

    unsigned ckA[2];
    ckA[0] = (unsigned)__cvta_generic_to_shared(Ck0);
    ckA[1] = (unsigned)__cvta_generic_to_shared(Ck1);

    const float* colbase = ColM + (size_t)bh*LCOL*16;
    const float* vbase   = Vm   + (size_t)bh*LCOL*16;

    int kk = tid >> 2, qq = tid & 3;                 // for cp.async (tid<512)
    unsigned swoff = (unsigned)swz4(kk, qq) * 4u;

    // ---- phase 1: score tile (4 rows/warp, 32-col slice per warp) ----------
    {
        int rowg = warp % 5, cs = warp / 5;   // 5 row-groups x 4 col-slices
        float qa[4][16];
#pragma unroll
        for (int j = 0; j < 4; j++) {
            int rr = r0 + rowg*4 + j; if (rr > Lrow - 1) rr = Lrow - 1;
            const float4* qr = (const float4*)(RowM + ((size_t)bh*Lrow + rr)*16);
#pragma unroll
            for (int u = 0; u < 4; u++) {
                float4 a = qr[u];
                qa[j][u*4+0] = a.x; qa[j][u*4+1] = a.y;
                qa[j][u*4+2] = a.z; qa[j][u*4+3] = a.w;
            }
        }
        // prologue: chunks 0,1
        if (ldr) cpasync16(ckA[0] + swoff, colbase + (size_t)(0*128 + kk)*16 + qq*4);
        cpcommit();
        if (ldr) cpasync16(ckA[1] + swoff, colbase + (size_t)(1*128 + kk)*16 + qq*4);
        cpcommit();

        for (int c = 0; c < NC; c++) {
            if (c + 1 < NC) cpwait<1>(); else cpwait<0>();
            __syncthreads();
            const float* Ck = (c & 1) ? Ck1 : Ck0;
            int kl = cs*32 + lane;
            float s0 = 0.f, s1 = 0.f, s2 = 0.f, s3 = 0.f;
#pragma unroll
            for (int u = 0; u < 4; u++) {
                float4 k4 = *(const float4*)&Ck[swz4(kl, u)];
                s0 = fmaf(qa[0][u*4+0], k4.x, s0); s0 = fmaf(qa[0][u*4+1], k4.y, s0);
                s0 = fmaf(qa[0][u*4+2], k4.z, s0); s0 = fmaf(qa[0][u*4+3], k4.w, s0);
                s1 = fmaf(qa[1][u*4+0], k4.x, s1); s1 = fmaf(qa[1][u*4+1], k4.y, s1);
                s1 = fmaf(qa[1][u*4+2], k4.z, s1); s1 = fmaf(qa[1][u*4+3], k4.w, s1);
                s2 = fmaf(qa[2][u*4+0], k4.x, s2); s2 = fmaf(qa[2][u*4+1], k4.y, s2);
                s2 = fmaf(qa[2][u*4+2], k4.z, s2); s2 = fmaf(qa[2][u*4+3], k4.w, s2);
                s3 = fmaf(qa[3][u*4+0], k4.x, s3); s3 = fmaf(qa[3][u*4+1], k4.y, s3);
                s3 = fmaf(qa[3][u*4+2], k4.z, s3); s3 = fmaf(qa[3][u*4+3], k4.w, s3);
            }
            S[(rowg*4+0)*LCOL + c*128 + kl] = 0.125f*s0;
            S[(rowg*4+1)*LCOL + c*128 + kl] = 0.125f*s1;
            S[(rowg*4+2)*LCOL + c*128 + kl] = 0.125f*s2;
            S[(rowg*4+3)*LCOL + c*128 + kl] = 0.125f*s3;
            __syncthreads();
            if (c + 2 < NC) {
                if (ldr)
                    cpasync16(ckA[c & 1] + swoff,
                              colbase + (size_t)((c+2)*128 + kk)*16 + qq*4);
                cpcommit();
            }
        }
    }

    // prefetch V chunks 0,1 so they land during phase 2
    if (ldr) cpasync16(ckA[0] + swoff, vbase + (size_t)(0*128 + kk)*16 + qq*4);
    cpcommit();
    if (ldr) cpasync16(ckA[1] + swoff, vbase + (size_t)(1*128 + kk)*16 + qq*4);
    cpcommit();

    // ---- phase 2: entmax1.5 per row (warp = row), data in SMEM -------------
    {
        float4* Srow4 = (float4*)(S + warp*LCOL);

        float m = -1e30f, s1 = 0.f, s2 = 0.f;
#pragma unroll
        for (int t = 0; t < NT4; t++) {
            float4 x = Srow4[lane + 32*t];
            m = fmaxf(m, fmaxf(fmaxf(x.x, x.y), fmaxf(x.z, x.w)));
            s1 += x.x + x.y + x.z + x.w;
            s2 = fmaf(x.x, x.x, s2); s2 = fmaf(x.y, x.y, s2);
            s2 = fmaf(x.z, x.z, s2); s2 = fmaf(x.w, x.w, s2);
        }
#pragma unroll
        for (int o = 16; o > 0; o >>= 1) {
            m  = fmaxf(m, __shfl_xor_sync(0xffffffffu, m, o));
            s1 += __shfl_xor_sync(0xffffffffu, s1, o);
            s2 += __shfl_xor_sync(0xffffffffu, s2, o);
        }
        const float n = (float)LCOL;
        float mean = s1 / n - m;
        float var  = s2 / n - (s1 / n)*(s1 / n);
        float delta = (1.f - n*var) / n;
        float tau = mean - sqrtf(fmaxf(delta, 0.f));
        tau = fmaxf(tau, -1.0f);
        tau = fminf(tau, -1e-9f);
        float tm = m + tau;

        for (int it = 0; it < 12; it++) {
            float F = 0.f, G = 0.f;
#pragma unroll
            for (int t = 0; t < NT4; t++) {
                float4 x = Srow4[lane + 32*t];
                float d0 = fmaxf(x.x - tm, 0.f), d1 = fmaxf(x.y - tm, 0.f);
                float d2 = fmaxf(x.z - tm, 0.f), d3 = fmaxf(x.w - tm, 0.f);
                F = fmaf(d0, d0, F); G += d0;
                F = fmaf(d1, d1, F); G += d1;
                F = fmaf(d2, d2, F); G += d2;
                F = fmaf(d3, d3, F); G += d3;
            }
#pragma unroll
            for (int o = 16; o > 0; o >>= 1) {
                F += __shfl_xor_sync(0xffffffffu, F, o);
                G += __shfl_xor_sync(0xffffffffu, G, o);
            }
            float step = (F - 1.f) / (2.f*G);
            tau += step;
            tau = fmaxf(tau, -1.0f);
            tau = fminf(tau, -1e-9f);
            tm = m + tau;
            if (fabsf(step) < 1e-6f) break;
        }

        int row = r0 + warp;
        bool ok = row < Lrow;
        float4* Arow4 = (float4*)(Aout + ((size_t)bh*Lrow + (ok ? row : 0))*LCOL);
#pragma unroll
        for (int t = 0; t < NT4; t++) {
            float4 x = Srow4[lane + 32*t];
            float d0 = fmaxf(x.x - tm, 0.f), d1 = fmaxf(x.y - tm, 0.f);
            float d2 = fmaxf(x.z - tm, 0.f), d3 = fmaxf(x.w - tm, 0.f);
            float4 p = make_float4(d0*d0, d1*d1, d2*d2, d3*d3);
            Srow4[lane + 32*t] = p;
            if (ok) __stcs(&Arow4[lane + 32*t], p);
        }
    }
    __syncthreads();

    // ---- phase 3: split-k  O[row][d] = sum_k p[k] V[k][d] ------------------
    // warp w: row group rg = w%5 (4 rows), k-slice ks = w/5 (32 cols per chunk)
    {
        int rg = warp % 5, ks = warp / 5;
        float o[4][16];
#pragma unroll
        for (int r = 0; r < 4; r++)
#pragma unroll
            for (int d = 0; d < 16; d++) o[r][d] = 0.f;

        for (int c = 0; c < NC; c++) {
            if (c + 1 < NC) cpwait<1>(); else cpwait<0>();
            __syncthreads();
            const float* Ck = (c & 1) ? Ck1 : Ck0;
            int col = ks*32 + lane;
            float p0 = S[(rg*4+0)*LCOL + c*128 + col];
            float p1 = S[(rg*4+1)*LCOL + c*128 + col];
            float p2 = S[(rg*4+2)*LCOL + c*128 + col];
            float p3 = S[(rg*4+3)*LCOL + c*128 + col];
            float4 v0 = *(const float4*)&Ck[swz4(col,0)];
            float4 v1 = *(const float4*)&Ck[swz4(col,1)];
            float4 v2 = *(const float4*)&Ck[swz4(col,2)];
            float4 v3 = *(const float4*)&Ck[swz4(col,3)];
            float vv[16] = {v0.x,v0.y,v0.z,v0.w, v1.x,v1.y,v1.z,v1.w,
                            v2.x,v2.y,v2.z,v2.w, v3.x,v3.y,v3.z,v3.w};
#pragma unroll
            for (int d = 0; d < 16; d++) {
                o[0][d] = fmaf(p0, vv[d], o[0][d]);
                o[1][d] = fmaf(p1, vv[d], o[1][d]);
                o[2][d] = fmaf(p2, vv[d], o[2][d]);
                o[3][d] = fmaf(p3, vv[d], o[3][d]);
            }
            __syncthreads();
            if (c + 2 < NC) {
                if (ldr)
                    cpasync16(ckA[c & 1] + swoff,
                              vbase + (size_t)((c+2)*128 + kk)*16 + qq*4);
                cpcommit();
            }
        }

        // butterfly-reduce each accumulator over lanes
#pragma unroll
        for (int r = 0; r < 4; r++)
#pragma unroll
            for (int d = 0; d < 16; d++)
#pragma unroll
                for (int off = 16; off > 0; off >>= 1)
                    o[r][d] += __shfl_xor_sync(0xffffffffu, o[r][d], off);

        float val[4];
#pragma unroll
        for (int r = 0; r < 4; r++) {
            float vv = 0.f;
#pragma unroll
            for (int d = 0; d < 16; d++) if (lane == d) vv = o[r][d];
            val[r] = vv;
        }
        if (lane < 16) {
#pragma unroll
            for (int r = 0; r < 4; r++)
                Sp[ks*(ROWS*16) + (rg*4+r)*16 + lane] = val[r];
        }
    }
    __syncthreads();
    // combine 4 k-slices, write Omid
    for (int i = tid; i < ROWS*16; i += THREADS) {
        float s = Sp[i] + Sp[ROWS*16 + i] + Sp[2*ROWS*16 + i] + Sp[3*ROWS*16 + i];
        int r = i >> 4, d = i & 15;
        int row = r0 + r;
        if (row < Lrow) {
            int b = blockIdx.z, h = blockIdx.y;
            Omid[((size_t)(b*Lrow + row))*DM + h*16 + d] = s;
        }
    }
}

// ---------------- fused final x2: relu(LN(X@WO + bO + R@WR)) ----------------
// 64 rows/CTA, 256 threads, thread tile 8 rows x 4 cols, float4 over cc
__global__ __launch_bounds__(256)
void final2_kernel(const float* __restrict__ po1, const float* __restrict__ po2,
                   const float* __restrict__ qin, const float* __restrict__ kin,
                   const float* __restrict__ WO,  const float* __restrict__ bOv,
                   const float* __restrict__ WR,
                   const float* __restrict__ WO2, const float* __restrict__ bO2,
                   const float* __restrict__ WR2,
                   const float* __restrict__ gamma, const float* __restrict__ beta,
                   float* __restrict__ out)
{
    int ssel = blockIdx.y;
    int rows = ssel ? BB*LK : BB*LQ;
    size_t row0 = (size_t)blockIdx.x * 64;
    if (row0 >= (size_t)rows) return;
    const float* Xmid  = ssel ? po2 : po1;
    const float* Resid = ssel ? kin : qin;
    const float* WOp   = ssel ? WO2 : WO;
    const float* bOp   = ssel ? bO2 : bOv;
    const float* WRp   = ssel ? WR2 : WR;
    float* dst = out + (ssel ? (size_t)BB*LQ*DM : 0);

    extern __shared__ float sm[];
    float* Wo = sm;               // 128 x 132 transposed
    float* Wr = sm + 128*132;     // 128 x 132 transposed
    float* Xs = sm + 2*128*132;   // 64 x 128
    float* Rs = Xs + 64*128;      // 64 x 128
    float* Ys = Xs;               // reused after GEMM
    int tid = threadIdx.x;

    for (int i = tid; i < 128*128; i += 256) {
        int cc = i >> 7, c = i & 127;
        Wo[c*132 + cc] = WOp[i];
        Wr[c*132 + cc] = WRp[i];
    }
    {
        const float4* xb = (const float4*)(Xmid  + row0*DM);
        const float4* rb = (const float4*)(Resid + row0*DM);
        float4* Xs4 = (float4*)Xs; float4* Rs4 = (float4*)Rs;
        for (int i = tid; i < 64*32; i += 256) { Xs4[i] = xb[i]; Rs4[i] = rb[i]; }
    }
    __syncthreads();

    int c0  = (tid & 31) * 4;     // 4 consecutive output cols
    int r0t = (tid >> 5) * 8;     // 8 rows
    float acc[8][4];
#pragma unroll
    for (int j = 0; j < 4; j++) {
        float bv = bOp[c0 + j];
#pragma unroll
        for (int r = 0; r < 8; r++) acc[r][j] = bv;
    }
    for (int cc = 0; cc < 128; cc += 4) {
        float4 wo[4], wr[4];
#pragma unroll
        for (int j = 0; j < 4; j++) {
            wo[j] = *(const float4*)&Wo[(c0+j)*132 + cc];
            wr[j] = *(const float4*)&Wr[(c0+j)*132 + cc];
        }
#pragma unroll
        for (int r = 0; r < 8; r++) {
            float4 x4 = *(const float4*)&Xs[(r0t+r)*128 + cc];
            float4 r4 = *(const float4*)&Rs[(r0t+r)*128 + cc];
#pragma unroll
            for (int j = 0; j < 4; j++) {
                float a = acc[r][j];
                a = fmaf(x4.x, wo[j].x, a); a = fmaf(r4.x, wr[j].x, a);
                a = fmaf(x4.y, wo[j].y, a); a = fmaf(r4.y, wr[j].y, a);
                a = fmaf(x4.z, wo[j].z, a); a = fmaf(r4.z, wr[j].z, a);
                a = fmaf(x4.w, wo[j].w, a); a = fmaf(r4.w, wr[j].w, a);
                acc[r][j] = a;
            }
        }
    }
    __syncthreads();   // all reads of Xs/Rs done
#pragma unroll
    for (int r = 0; r < 8; r++)
        *(float4*)&Ys[(r0t+r)*128 + c0] =
            make_float4(acc[r][0], acc[r][1], acc[r][2], acc[r][3]);
    __syncthreads();

    int warp = tid >> 5, lane = tid & 31;
    for (int rr = warp; rr < 64; rr += 8) {
        float v0 = Ys[rr*DM + lane],      v1 = Ys[rr*DM + lane + 32];
        float v2 = Ys[rr*DM + lane + 64], v3 = Ys[rr*DM + lane + 96];
        float s = v0 + v1 + v2 + v3;
#pragma unroll
        for (int o = 16; o > 0; o >>= 1) s += __shfl_xor_sync(0xffffffffu, s, o);
        float mu = s * (1.f/128.f);
        float d0 = v0-mu, d1 = v1-mu, d2 = v2-mu, d3 = v3-mu;
        float vs = d0*d0 + d1*d1 + d2*d2 + d3*d3;
#pragma unroll
        for (int o = 16; o > 0; o >>= 1) vs += __shfl_xor_sync(0xffffffffu, vs, o);
        float inv = rsqrtf(vs * (1.f/128.f) + EPSV);
        float* drow = dst + (row0 + rr)*DM;
        drow[lane]      = fmaxf(gamma[lane]     *d0*inv + beta[lane],      0.f);
        drow[lane + 32] = fmaxf(gamma[lane + 32]*d1*inv + beta[lane + 32], 0.f);
        drow[lane + 64] = fmaxf(gamma[lane + 64]*d2*inv + beta[lane + 64], 0.f);
        drow[lane + 96] = fmaxf(gamma[lane + 96]*d3*inv + beta[lane + 96], 0.f);
    }
}

// ---------------- host launcher ----------------------------------------------
extern "C" void kernel_launch(void* const* d_in, const int* in_sizes, int n_in,
                              void* d_out, int out_size)
{
    const float* q    = (const float*)d_in[0];
    const float* k    = (const float*)d_in[1];
    const float* v    = (const float*)d_in[2];
    const float* v2   = (const float*)d_in[3];
    const float* W_Q  = (const float*)d_in[4];
    const float* b_Q  = (const float*)d_in[5];
    const float* W_K  = (const float*)d_in[6];
    const float* b_K  = (const float*)d_in[7];
    const float* W_V  = (const float*)d_in[8];
    const float* b_V  = (const float*)d_in[9];
    const float* W_V2 = (const float*)d_in[10];
    const float* b_V2 = (const float*)d_in[11];
    const float* W_O  = (const float*)d_in[12];
    const float* b_O  = (const float*)d_in[13];
    const float* W_O2 = (const float*)d_in[14];
    const float* b_O2 = (const float*)d_in[15];
    const float* W_R  = (const float*)d_in[16];
    const float* W_R2 = (const float*)d_in[17];
    const float* gamma= (const float*)d_in[18];
    const float* beta = (const float*)d_in[19];
    float* out = (float*)d_out;

    float *pQ, *pK, *pV, *pV2, *po1, *po2;
    cudaGetSymbolAddress((void**)&pQ,  g_Q);
    cudaGetSymbolAddress((void**)&pK,  g_K);
    cudaGetSymbolAddress((void**)&pV,  g_V);
    cudaGetSymbolAddress((void**)&pV2, g_V2);
    cudaGetSymbolAddress((void**)&po1, g_o1);
    cudaGetSymbolAddress((void**)&po2, g_o2);

    const int PROJ_SMEM = (128*132 + 16*128) * 4;               // 75776
    const int ATT1_SMEM = (20*LK + 2*2048 + 4*20*16) * 4;       // 185344
    const int ATT2_SMEM = (20*LQ + 2*2048 + 4*20*16) * 4;       // 103424
    const int FIN_SMEM  = (2*128*132 + 2*64*128) * 4;           // 200704
    cudaFuncSetAttribute(proj4_kernel,  cudaFuncAttributeMaxDynamicSharedMemorySize, PROJ_SMEM);
    cudaFuncSetAttribute(attn_kernel<LK>, cudaFuncAttributeMaxDynamicSharedMemorySize, ATT1_SMEM);
    cudaFuncSetAttribute(attn_kernel<LQ>, cudaFuncAttributeMaxDynamicSharedMemorySize, ATT2_SMEM);
    cudaFuncSetAttribute(final2_kernel, cudaFuncAttributeMaxDynamicSharedMemorySize, FIN_SMEM);

    proj4_kernel<<<dim3(LK/16, BB, 4), 256, PROJ_SMEM>>>(
        q, k, v, v2, W_Q, b_Q, W_K, b_K, W_V, b_V, W_V2, b_V2, pQ, pK, pV, pV2);

    // d_out layout: out [B,Lq,128] | out2 [B,Lk,128] | A [B,H,Lq,Lk] | A2 [B,H,Lk,Lq]
    float* Aout  = out + ((size_t)BB*LQ*DM + (size_t)BB*LK*DM);
    float* A2out = Aout + (size_t)BB*HH*LQ*LK;

    attn_kernel<LK><<<dim3((LQ + 19)/20, HH, BB), 640, ATT1_SMEM>>>(
        pQ, pK, pV,  Aout,  po1, LQ);
    attn_kernel<LQ><<<dim3((LK + 19)/20, HH, BB), 640, ATT2_SMEM>>>(
        pK, pQ, pV2, A2out, po2, LK);

    final2_kernel<<<dim3(BB*LK/64, 2), 256, FIN_SMEM>>>(
        po1, po2, q, k, W_O, b_O, W_R, W_O2, b_O2, W_R2, gamma, beta, out);
}